// round 14
// baseline (speedup 1.0000x reference)
#include <cuda_runtime.h>
#include <cuda_fp16.h>
#include <cstdint>

#define L_DIM 4096
#define B_DIM 4
#define E_DIM 1024
#define H_DIM 16
#define HD 64
#define NH 64            // B*H
#define M_TOT 16384      // L*B
#define EPS_F 1e-4f
#define ANG_C 3.83495196971410283e-4f   // (pi/2)/4096
#define KCH 16           // kv2 L-chunks
#define OCH 8            // out2 L-chunks

// ---------------- scratch (device globals; no allocs allowed) ----------------
__device__ __half g_qh[NH * L_DIM * HD];               // relu(Q), fp16, head-major
__device__ __half g_kh[NH * L_DIM * HD];               // relu(K), fp16
__device__ __half g_vh[NH * L_DIM * HD];               // V, fp16
__device__ __half g_xh[3 * M_TOT * E_DIM];             // fp16, pair-permuted X (q,k,v)
__device__ __half g_wh[3 * E_DIM * E_DIM];             // fp16, pair-permuted W (q,k,v)
__device__ float g_kv_part[NH * KCH * 2 * HD * HD];    // per-chunk partial kv [d128][m64]
__device__ float g_ks_part[NH * KCH * 256];            // per-chunk partial ksum (2 halves x 128)
__device__ float g_kv[NH * 2 * HD * HD];               // reduced kv
__device__ float g_ks[NH * 2 * HD];                    // reduced ksum

__device__ __forceinline__ unsigned f2tf32(float x) {
    unsigned r;
    asm("cvt.rna.tf32.f32 %0, %1;" : "=r"(r) : "f"(x));
    return r;
}
__device__ __forceinline__ float ftf(float x) { return __uint_as_float(f2tf32(x)); }

// position of scalar d within a pair-permuted 16-element group layout
__device__ __forceinline__ int permpos(int d) {
    const int g = d >> 4, j = (d >> 1) & 7, o = d & 1;
    const int jp = (j < 4) ? (2 * j) : (2 * (j - 4) + 1);
    return (g << 4) + (jp << 1) + o;
}

__device__ __forceinline__ void mma_tf32(float c[4],
                                         unsigned a0, unsigned a1, unsigned a2, unsigned a3,
                                         unsigned b0, unsigned b1) {
    asm volatile(
        "mma.sync.aligned.m16n8k8.row.col.f32.tf32.tf32.f32 "
        "{%0,%1,%2,%3}, {%4,%5,%6,%7}, {%8,%9}, {%0,%1,%2,%3};\n"
        : "+f"(c[0]), "+f"(c[1]), "+f"(c[2]), "+f"(c[3])
        : "r"(a0), "r"(a1), "r"(a2), "r"(a3), "r"(b0), "r"(b1));
}

__device__ __forceinline__ void mma_f16(float c[4],
                                        unsigned a0, unsigned a1, unsigned a2, unsigned a3,
                                        unsigned b0, unsigned b1) {
    asm volatile(
        "mma.sync.aligned.m16n8k16.row.col.f32.f16.f16.f32 "
        "{%0,%1,%2,%3}, {%4,%5,%6,%7}, {%8,%9}, {%0,%1,%2,%3};\n"
        : "+f"(c[0]), "+f"(c[1]), "+f"(c[2]), "+f"(c[3])
        : "r"(a0), "r"(a1), "r"(a2), "r"(a3), "r"(b0), "r"(b1));
}

__device__ __forceinline__ void cpa16(void* dst, const void* src) {
    unsigned d = (unsigned)__cvta_generic_to_shared(dst);
    asm volatile("cp.async.cg.shared.global [%0], [%1], 16;\n" :: "r"(d), "l"(src));
}

// ---------------- Phase 0: fp16-round + pair-permute X and W (fused) ----------------
__global__ __launch_bounds__(256) void preround_xw(
    const float4* __restrict__ xq, const float4* __restrict__ xk, const float4* __restrict__ xv,
    const float4* __restrict__ wq, const float4* __restrict__ wk, const float4* __restrict__ wv)
{
    const int bx = blockIdx.x;
    const int z = blockIdx.y;
    const bool isX = (bx < 4096);
    const int g = (isX ? bx : (bx - 4096)) * 256 + threadIdx.x;
    const float4* src = isX ? ((z == 0) ? xq : (z == 1) ? xk : xv)
                            : ((z == 0) ? wq : (z == 1) ? wk : wv);
    const float4 f0 = src[4 * g + 0];
    const float4 f1 = src[4 * g + 1];
    const float4 f2 = src[4 * g + 2];
    const float4 f3 = src[4 * g + 3];
    __half2 h[8];
    h[0] = __floats2half2_rn(f0.x, f0.y);   // p0
    h[1] = __floats2half2_rn(f2.x, f2.y);   // p4
    h[2] = __floats2half2_rn(f0.z, f0.w);   // p1
    h[3] = __floats2half2_rn(f2.z, f2.w);   // p5
    h[4] = __floats2half2_rn(f1.x, f1.y);   // p2
    h[5] = __floats2half2_rn(f3.x, f3.y);   // p6
    h[6] = __floats2half2_rn(f1.z, f1.w);   // p3
    h[7] = __floats2half2_rn(f3.z, f3.w);   // p7
    float4* dst = isX ? ((float4*)g_xh + (size_t)z * 2097152 + 2 * (size_t)g)
                      : ((float4*)g_wh + (size_t)z * 131072 + 2 * (size_t)g);
    dst[0] = *(float4*)&h[0];
    dst[1] = *(float4*)&h[4];
}

// ---------------- Phase 1: fused QKV projection (fp16 m16n8k16) ----------------
// 128x128 CTA tile, 4 warps, 64x64 warptile, paired-ktile double buffer, stride 48.
#define SSTRH 48
#define STGH (128 * SSTRH)           // halves per matrix per ktile (6144)
#define SUPER (4 * STGH)             // halves per super-buffer (A0,A1,B0,B1)

__global__ __launch_bounds__(128, 2) void gemm_qkv(
    const float* __restrict__ bq, const float* __restrict__ bk, const float* __restrict__ bv)
{
    extern __shared__ __half smh[];  // [2 super][A0 | A1 | B0 | B1]

    const int z = blockIdx.z;
    const __half* X   = g_xh + (size_t)z * (M_TOT * E_DIM);
    const __half* W   = g_wh + (size_t)z * (E_DIM * E_DIM);
    const float* bias = (z == 0) ? bq : (z == 1) ? bk : bv;
    __half* dst       = (z == 0) ? g_qh : (z == 1) ? g_kh : g_vh;
    const bool do_relu = (z < 2);

    const int m0 = blockIdx.y * 128;
    const int n0 = blockIdx.x * 128;
    const int t = threadIdx.x;
    const int lane = t & 31, warp = t >> 5;
    const int wm = (warp & 1) * 64, wn = (warp >> 1) * 64;
    const int gid = lane >> 2, tig = lane & 3;

    const int lr2 = t >> 1;          // 0..63 (row in 64-row group)
    const int seg = (t & 1) * 16;    // halves offset: 0 or 16
    const __half* Ag = X + (size_t)m0 * E_DIM;
    const __half* Bg = W + (size_t)n0 * E_DIM;

    float acc[4][8][4];
#pragma unroll
    for (int i = 0; i < 4; ++i)
#pragma unroll
        for (int j = 0; j < 8; ++j)
#pragma unroll
            for (int e = 0; e < 4; ++e) acc[i][j][e] = 0.f;

    // stage super j = ktiles 2j, 2j+1 into buffer j&1
    auto stage = [&](int j) {
        __half* base = smh + (j & 1) * SUPER;
#pragma unroll
        for (int sub = 0; sub < 2; ++sub) {
            const int kt = 2 * j + sub;
            __half* sA = base + sub * STGH;
            __half* sB = base + 2 * STGH + sub * STGH;
#pragma unroll
            for (int i = 0; i < 2; ++i) {
                const int row = lr2 + i * 64;
#pragma unroll
                for (int c = 0; c < 2; ++c) {
                    cpa16(&sA[row * SSTRH + seg + c * 8],
                          Ag + (size_t)row * E_DIM + kt * 32 + seg + c * 8);
                    cpa16(&sB[row * SSTRH + seg + c * 8],
                          Bg + (size_t)row * E_DIM + kt * 32 + seg + c * 8);
                }
            }
        }
        asm volatile("cp.async.commit_group;\n");
    };

    stage(0);
#pragma unroll 1
    for (int j = 0; j < 16; ++j) {
        asm volatile("cp.async.wait_group 0;\n");
        __syncthreads();
        if (j < 15) stage(j + 1);
        const __half* base = smh + (j & 1) * SUPER;
#pragma unroll
        for (int sub = 0; sub < 2; ++sub) {
            const __half* sA = base + sub * STGH;
            const __half* sB = base + 2 * STGH + sub * STGH;
#pragma unroll
            for (int s = 0; s < 2; ++s) {
                const int kpos = s * 16 + tig * 4;
                uint2 aF[4][2];
                uint2 bF[8];
#pragma unroll
                for (int mf = 0; mf < 4; ++mf) {
                    const int r = wm + mf * 16 + gid;
                    aF[mf][0] = *(const uint2*)&sA[r * SSTRH + kpos];
                    aF[mf][1] = *(const uint2*)&sA[(r + 8) * SSTRH + kpos];
                }
#pragma unroll
                for (int nf = 0; nf < 8; ++nf) {
                    const int cb = wn + nf * 8 + gid;
                    bF[nf] = *(const uint2*)&sB[cb * SSTRH + kpos];
                }
#pragma unroll
                for (int mf = 0; mf < 4; ++mf)
#pragma unroll
                    for (int nf = 0; nf < 8; ++nf)
                        mma_f16(acc[mf][nf],
                                aF[mf][0].x, aF[mf][1].x, aF[mf][0].y, aF[mf][1].y,
                                bF[nf].x, bF[nf].y);
            }
        }
    }

    // epilogue: bias + relu + fp16 + scatter to [head][l][hd] (half2 stores)
#pragma unroll
    for (int mf = 0; mf < 4; ++mf) {
#pragma unroll
        for (int nf = 0; nf < 8; ++nf) {
            const int row = m0 + wm + mf * 16 + gid;
            const int col = n0 + wn + nf * 8 + tig * 2;   // even
            const float b0 = __ldg(&bias[col]);
            const float b1 = __ldg(&bias[col + 1]);
            const int hh = col >> 6, hd = col & 63;
#pragma unroll
            for (int half8 = 0; half8 < 2; ++half8) {
                const int r = row + half8 * 8;
                float v0 = acc[mf][nf][half8 * 2 + 0] + b0;
                float v1 = acc[mf][nf][half8 * 2 + 1] + b1;
                if (do_relu) { v0 = fmaxf(v0, 0.f); v1 = fmaxf(v1, 0.f); }
                const int l = r >> 2, bb = r & 3;
                const int head = bb * H_DIM + hh;
                *(__half2*)&dst[((size_t)head << 18) + ((size_t)l << 6) + (size_t)hd] =
                    __floats2half2_rn(v0, v1);
            }
        }
    }
}

// ---------------- Phase 2: kv = k_^T v, fp16 inputs, register-prefetch, tf32 MMA ----------------
// grid (NH, KCH): 256 l per chunk, 8 tiles of 32.
__global__ __launch_bounds__(256, 2) void kv2() {
    __shared__ float Ks[32 * 136];   // [l][128 scaled d], stride 136
    __shared__ float Vs[32 * 72];    // [l][64 m], stride 72

    const int h = blockIdx.x, ch = blockIdx.y;
    const int t = threadIdx.x, lane = t & 31, warp = t >> 5;
    const int wm = (warp >> 1) * 32, wn = (warp & 1) * 32;
    const int gid = lane >> 2, tig = lane & 3;

    float acc[2][4][4];
#pragma unroll
    for (int mf = 0; mf < 2; ++mf)
#pragma unroll
        for (int nf = 0; nf < 4; ++nf)
#pragma unroll
            for (int e = 0; e < 4; ++e) acc[mf][nf][e] = 0.f;
    float ksacc = 0.f;

    const __half* kp = g_kh + ((size_t)h << 18);
    const __half* vp = g_vh + ((size_t)h << 18);
    const int ll = t >> 3;
    const int f = (t & 7) * 8;
    const int ch0 = ch * 256;
    const int kd = t & 127;          // ksum: d index
    const int kj0 = (t >> 7) * 16;   // ksum: j half

    uint4 kraw, vraw;   // 8 halves each
    {
        const size_t b = (size_t)(ch0 + ll) * 64 + f;
        kraw = *(const uint4*)(kp + b);
        vraw = *(const uint4*)(vp + b);
    }

#pragma unroll 1
    for (int it = 0; it < 8; ++it) {
        {
            const int l = ch0 + it * 32 + ll;
            float s, c;
            sincosf(ANG_C * (float)(l + 1), &s, &c);
            const __half2* kh2 = (const __half2*)&kraw;
            const __half2* vh2 = (const __half2*)&vraw;
            float kf[8], vf[8];
#pragma unroll
            for (int j = 0; j < 4; ++j) {
                const float2 kj = __half22float2(kh2[j]);
                const float2 vj = __half22float2(vh2[j]);
                kf[2 * j] = kj.x; kf[2 * j + 1] = kj.y;
                vf[2 * j] = vj.x; vf[2 * j + 1] = vj.y;
            }
#pragma unroll
            for (int j = 0; j < 8; ++j) {
                Ks[ll * 136 + f + j]      = ftf(kf[j] * s);
                Ks[ll * 136 + 64 + f + j] = ftf(kf[j] * c);
                Vs[ll * 72 + f + j]       = ftf(vf[j]);
            }
        }
        __syncthreads();
        if (it < 7) {
            const size_t b = (size_t)(ch0 + (it + 1) * 32 + ll) * 64 + f;
            kraw = *(const uint4*)(kp + b);
            vraw = *(const uint4*)(vp + b);
        }
#pragma unroll
        for (int j = 0; j < 16; ++j) ksacc += Ks[(kj0 + j) * 136 + kd];
#pragma unroll
        for (int k8 = 0; k8 < 4; ++k8) {
            const int kk = k8 * 8;
            unsigned af[2][4], bf[4][2];
#pragma unroll
            for (int mf = 0; mf < 2; ++mf) {
                const int r = wm + mf * 16 + gid;
                af[mf][0] = __float_as_uint(Ks[(kk + tig) * 136 + r]);
                af[mf][1] = __float_as_uint(Ks[(kk + tig) * 136 + r + 8]);
                af[mf][2] = __float_as_uint(Ks[(kk + tig + 4) * 136 + r]);
                af[mf][3] = __float_as_uint(Ks[(kk + tig + 4) * 136 + r + 8]);
            }
#pragma unroll
            for (int nf = 0; nf < 4; ++nf) {
                const int cb = wn + nf * 8 + gid;
                bf[nf][0] = __float_as_uint(Vs[(kk + tig) * 72 + cb]);
                bf[nf][1] = __float_as_uint(Vs[(kk + tig + 4) * 72 + cb]);
            }
#pragma unroll
            for (int mf = 0; mf < 2; ++mf)
#pragma unroll
                for (int nf = 0; nf < 4; ++nf)
                    mma_tf32(acc[mf][nf], af[mf][0], af[mf][1], af[mf][2], af[mf][3],
                             bf[nf][0], bf[nf][1]);
        }
        __syncthreads();
    }

    float* outp = g_kv_part + (size_t)(h * KCH + ch) * 8192;
#pragma unroll
    for (int mf = 0; mf < 2; ++mf) {
#pragma unroll
        for (int nf = 0; nf < 4; ++nf) {
            const int row = wm + mf * 16 + gid;
            const int col = wn + nf * 8 + tig * 2;
            *(float2*)&outp[row * 64 + col] = make_float2(acc[mf][nf][0], acc[mf][nf][1]);
            *(float2*)&outp[(row + 8) * 64 + col] = make_float2(acc[mf][nf][2], acc[mf][nf][3]);
        }
    }
    g_ks_part[(size_t)(h * KCH + ch) * 256 + t] = ksacc;
}

// ---------------- Phase 2b: reduce partials ----------------
__global__ __launch_bounds__(256) void reduce_kv() {
    const int h = blockIdx.x, seg = blockIdx.y, t = threadIdx.x;
    if (seg < 8) {
        const int base = seg * 1024;
#pragma unroll
        for (int r = 0; r < 4; ++r) {
            const int i = base + r * 256 + t;
            float s = 0.f;
#pragma unroll
            for (int p = 0; p < KCH; ++p)
                s += g_kv_part[(size_t)(h * KCH + p) * 8192 + i];
            g_kv[(size_t)h * 8192 + i] = s;
        }
    } else if (t < 128) {
        float s = 0.f;
#pragma unroll
        for (int p = 0; p < KCH; ++p) {
            const float* sp = g_ks_part + (size_t)(h * KCH + p) * 256;
            s += sp[t] + sp[128 + t];
        }
        g_ks[h * 128 + t] = s;
    }
}

// ---------------- Phase 3: out = (q_ @ kv) * z, fp16 m16n8k16 ----------------
#define OSTR 144

__global__ __launch_bounds__(256, 2) void out2(float* __restrict__ out) {
    extern __shared__ char sm3raw[];
    __half* KVh  = (__half*)sm3raw;                       // 64*144*2  = 18432 B
    __half* Qh   = (__half*)(sm3raw + 18432);             // 128*144*2 = 36864 B
    float*  kssP = (float*)(sm3raw + 18432 + 36864);      // 128 floats (permuted order)
    float*  zden = kssP + 128;                            // 128 floats
    float*  smemF = (float*)(sm3raw + 18432);             // transient: overlaps Qh (32768 B)

    const int h = blockIdx.x, ch = blockIdx.y;
    const int t = threadIdx.x, lane = t & 31, warp = t >> 5;
    const int wm = (warp >> 1) * 32, wn = (warp & 1) * 32;
    const int gid = lane >> 2, tig = lane & 3;

    for (int i = t; i < 8192; i += 256) smemF[i] = g_kv[(size_t)h * 8192 + i];
    if (t < 128) kssP[permpos(t)] = g_ks[h * 128 + t];
    __syncthreads();

    {
        const int m = t & 63, q4 = t >> 6;
#pragma unroll
        for (int dd = 0; dd < 32; ++dd) {
            const int d = q4 * 32 + dd;
            KVh[m * OSTR + permpos(d)] = __float2half(smemF[d * 64 + m]);
        }
    }
    __syncthreads();

    const __half* qp = g_qh + ((size_t)h << 18);
    const int bb = h >> 4, hh = h & 15;

#pragma unroll 1
    for (int it = 0; it < 4; ++it) {
        const int l0 = ch * 512 + it * 128;
        {
            const int lq = t >> 1;
            const int fq = (t & 1) * 32;
            const int l = l0 + lq;
            float s, c;
            sincosf(ANG_C * (float)(l + 1), &s, &c);
            const __half* qrow = qp + (size_t)l * 64 + fq;
            const uint4 qr0 = *(const uint4*)(qrow + 0);
            const uint4 qr1 = *(const uint4*)(qrow + 8);
            const uint4 qr2 = *(const uint4*)(qrow + 16);
            const uint4 qr3 = *(const uint4*)(qrow + 24);
            float qvall[32];
#pragma unroll
            for (int j = 0; j < 4; ++j) {
                const float2 a  = __half22float2(((const __half2*)&qr0)[j]);
                qvall[2 * j] = a.x;       qvall[2 * j + 1] = a.y;
                const float2 b2 = __half22float2(((const __half2*)&qr1)[j]);
                qvall[8 + 2 * j] = b2.x;  qvall[9 + 2 * j] = b2.y;
                const float2 c2 = __half22float2(((const __half2*)&qr2)[j]);
                qvall[16 + 2 * j] = c2.x; qvall[17 + 2 * j] = c2.y;
                const float2 d2 = __half22float2(((const __half2*)&qr3)[j]);
                qvall[24 + 2 * j] = d2.x; qvall[25 + 2 * j] = d2.y;
            }
#pragma unroll
            for (int g2 = 0; g2 < 2; ++g2) {
                const float* qv = &qvall[g2 * 16];
                __half2 hs[8], hc[8];
#pragma unroll
                for (int j = 0; j < 4; ++j) {
                    hs[2 * j]     = __floats2half2_rn(qv[2 * j] * s, qv[2 * j + 1] * s);
                    hs[2 * j + 1] = __floats2half2_rn(qv[8 + 2 * j] * s, qv[9 + 2 * j] * s);
                    hc[2 * j]     = __floats2half2_rn(qv[2 * j] * c, qv[2 * j + 1] * c);
                    hc[2 * j + 1] = __floats2half2_rn(qv[8 + 2 * j] * c, qv[9 + 2 * j] * c);
                }
                const int baseS = lq * OSTR + fq + g2 * 16;
                const int baseC = lq * OSTR + 64 + fq + g2 * 16;
                *(float4*)&Qh[baseS]     = *(float4*)&hs[0];
                *(float4*)&Qh[baseS + 8] = *(float4*)&hs[4];
                *(float4*)&Qh[baseC]     = *(float4*)&hc[0];
                *(float4*)&Qh[baseC + 8] = *(float4*)&hc[4];
            }
        }
        __syncthreads();
        {
            const int lz = t >> 1;
            const int dh = (t & 1) * 64;
            float p = 0.f;
#pragma unroll
            for (int j = 0; j < 32; ++j) {
                const __half2 hv = *(const __half2*)&Qh[lz * OSTR + dh + 2 * j];
                const float2 fv = __half22float2(hv);
                p += fv.x * kssP[dh + 2 * j] + fv.y * kssP[dh + 2 * j + 1];
            }
            p += __shfl_xor_sync(0xffffffffu, p, 1);
            if ((t & 1) == 0) zden[lz] = 1.0f / fmaxf(p, EPS_F);
        }
        __syncthreads();

        float acc[2][4][4];
#pragma unroll
        for (int mf = 0; mf < 2; ++mf)
#pragma unroll
            for (int nf = 0; nf < 4; ++nf)
#pragma unroll
                for (int e = 0; e < 4; ++e) acc[mf][nf][e] = 0.f;

#pragma unroll
        for (int k16 = 0; k16 < 8; ++k16) {
            const int kpos = k16 * 16 + tig * 4;
            uint2 aF[2][2];
            uint2 bF[4];
#pragma unroll
            for (int mf = 0; mf < 2; ++mf) {
                const int r = wm + mf * 16 + gid;
                aF[mf][0] = *(const uint2*)&Qh[r * OSTR + kpos];
                aF[mf][1] = *(const uint2*)&Qh[(r + 8) * OSTR + kpos];
            }
#pragma unroll
            for (int nf = 0; nf < 4; ++nf) {
                const int cb = wn + nf * 8 + gid;
                bF[nf] = *(const uint2*)&KVh[cb * OSTR + kpos];
            }
#pragma unroll
            for (int mf = 0; mf < 2; ++mf)
#pragma unroll
                for (int nf = 0; nf < 4; ++nf)
                    mma_f16(acc[mf][nf],
                            aF[mf][0].x, aF[mf][1].x, aF[mf][0].y, aF[mf][1].y,
                            bF[nf].x, bF[nf].y);
        }

#pragma unroll
        for (int mf = 0; mf < 2; ++mf) {
#pragma unroll
            for (int nf = 0; nf < 4; ++nf) {
                const int rl = wm + mf * 16 + gid;
                const int col = hh * 64 + wn + nf * 8 + tig * 2;
                const float z0 = zden[rl];
                const float z1 = zden[rl + 8];
                const int l_a = l0 + rl;
                const int l_b = l_a + 8;
                *(float2*)&out[((size_t)l_a * B_DIM + bb) * E_DIM + col] =
                    make_float2(acc[mf][nf][0] * z0, acc[mf][nf][1] * z0);
                *(float2*)&out[((size_t)l_b * B_DIM + bb) * E_DIM + col] =
                    make_float2(acc[mf][nf][2] * z1, acc[mf][nf][3] * z1);
            }
        }
        __syncthreads();
    }
}

// ---------------- launch ----------------
extern "C" void kernel_launch(void* const* d_in, const int* in_sizes, int n_in,
                              void* d_out, int out_size) {
    const float* q  = (const float*)d_in[0];
    const float* k  = (const float*)d_in[1];
    const float* v  = (const float*)d_in[2];
    const float* Wq = (const float*)d_in[3];
    const float* bq = (const float*)d_in[4];
    const float* Wk = (const float*)d_in[5];
    const float* bk = (const float*)d_in[6];
    const float* Wv = (const float*)d_in[7];
    const float* bv = (const float*)d_in[8];
    float* out = (float*)d_out;

    const int smem1 = 2 * SUPER * 2;                        // 98304 B
    const int smem3 = 18432 + 36864 + 512 + 512;            // 56320 B
    cudaFuncSetAttribute(gemm_qkv, cudaFuncAttributeMaxDynamicSharedMemorySize, smem1);
    cudaFuncSetAttribute(out2, cudaFuncAttributeMaxDynamicSharedMemorySize, smem3);

    preround_xw<<<dim3(4352, 3), 256>>>((const float4*)q, (const float4*)k, (const float4*)v,
                                        (const float4*)Wq, (const float4*)Wk, (const float4*)Wv);
    dim3 g1(E_DIM / 128, M_TOT / 128, 3);   // (8, 128, 3)
    gemm_qkv<<<g1, 128, smem1>>>(bq, bk, bv);
    kv2<<<dim3(NH, KCH), 256>>>();
    reduce_kv<<<dim3(NH, 9), 256>>>();
    out2<<<dim3(NH, OCH), 256, smem3>>>(out);
}

// round 15
// speedup vs baseline: 1.1975x; 1.1975x over previous
#include <cuda_runtime.h>
#include <cuda_fp16.h>
#include <cstdint>

#define L_DIM 4096
#define B_DIM 4
#define E_DIM 1024
#define H_DIM 16
#define HD 64
#define NH 64            // B*H
#define M_TOT 16384      // L*B
#define EPS_F 1e-4f
#define ANG_C 3.83495196971410283e-4f   // (pi/2)/4096
#define KCH 16           // kv2 L-chunks
#define OCH 8            // out2 L-chunks

// ---------------- scratch (device globals; no allocs allowed) ----------------
__device__ __half g_qh[NH * L_DIM * HD];               // relu(Q), fp16, head-major
__device__ __half g_kh[NH * L_DIM * HD];               // relu(K), fp16
__device__ __half g_vh[NH * L_DIM * HD];               // V, fp16
__device__ __half g_xh[3 * M_TOT * E_DIM];             // fp16, pair-permuted X (q,k,v)
__device__ __half g_wh[3 * E_DIM * E_DIM];             // fp16, pair-permuted W (q,k,v)
__device__ float g_kv_part[NH * KCH * 2 * HD * HD];    // per-chunk partial kv [d128][m64]
__device__ float g_ks_part[NH * KCH * 256];            // per-chunk partial ksum (2 halves x 128)
__device__ float g_kv[NH * 2 * HD * HD];               // reduced kv
__device__ float g_ks[NH * 2 * HD];                    // reduced ksum

__device__ __forceinline__ unsigned f2tf32(float x) {
    unsigned r;
    asm("cvt.rna.tf32.f32 %0, %1;" : "=r"(r) : "f"(x));
    return r;
}
__device__ __forceinline__ float ftf(float x) { return __uint_as_float(f2tf32(x)); }

// position of scalar d within a pair-permuted 16-element group layout
__device__ __forceinline__ int permpos(int d) {
    const int g = d >> 4, j = (d >> 1) & 7, o = d & 1;
    const int jp = (j < 4) ? (2 * j) : (2 * (j - 4) + 1);
    return (g << 4) + (jp << 1) + o;
}

__device__ __forceinline__ void mma_tf32(float c[4],
                                         unsigned a0, unsigned a1, unsigned a2, unsigned a3,
                                         unsigned b0, unsigned b1) {
    asm volatile(
        "mma.sync.aligned.m16n8k8.row.col.f32.tf32.tf32.f32 "
        "{%0,%1,%2,%3}, {%4,%5,%6,%7}, {%8,%9}, {%0,%1,%2,%3};\n"
        : "+f"(c[0]), "+f"(c[1]), "+f"(c[2]), "+f"(c[3])
        : "r"(a0), "r"(a1), "r"(a2), "r"(a3), "r"(b0), "r"(b1));
}

__device__ __forceinline__ void mma_f16(float c[4],
                                        unsigned a0, unsigned a1, unsigned a2, unsigned a3,
                                        unsigned b0, unsigned b1) {
    asm volatile(
        "mma.sync.aligned.m16n8k16.row.col.f32.f16.f16.f32 "
        "{%0,%1,%2,%3}, {%4,%5,%6,%7}, {%8,%9}, {%0,%1,%2,%3};\n"
        : "+f"(c[0]), "+f"(c[1]), "+f"(c[2]), "+f"(c[3])
        : "r"(a0), "r"(a1), "r"(a2), "r"(a3), "r"(b0), "r"(b1));
}

__device__ __forceinline__ void cpa16(void* dst, const void* src) {
    unsigned d = (unsigned)__cvta_generic_to_shared(dst);
    asm volatile("cp.async.cg.shared.global [%0], [%1], 16;\n" :: "r"(d), "l"(src));
}

// ---------------- Phase 0: fp16-round + pair-permute X and W (fused) ----------------
__global__ __launch_bounds__(256) void preround_xw(
    const float4* __restrict__ xq, const float4* __restrict__ xk, const float4* __restrict__ xv,
    const float4* __restrict__ wq, const float4* __restrict__ wk, const float4* __restrict__ wv)
{
    const int bx = blockIdx.x;
    const int z = blockIdx.y;
    const bool isX = (bx < 4096);
    const int g = (isX ? bx : (bx - 4096)) * 256 + threadIdx.x;
    const float4* src = isX ? ((z == 0) ? xq : (z == 1) ? xk : xv)
                            : ((z == 0) ? wq : (z == 1) ? wk : wv);
    const float4 f0 = src[4 * g + 0];
    const float4 f1 = src[4 * g + 1];
    const float4 f2 = src[4 * g + 2];
    const float4 f3 = src[4 * g + 3];
    __half2 h[8];
    h[0] = __floats2half2_rn(f0.x, f0.y);   // p0
    h[1] = __floats2half2_rn(f2.x, f2.y);   // p4
    h[2] = __floats2half2_rn(f0.z, f0.w);   // p1
    h[3] = __floats2half2_rn(f2.z, f2.w);   // p5
    h[4] = __floats2half2_rn(f1.x, f1.y);   // p2
    h[5] = __floats2half2_rn(f3.x, f3.y);   // p6
    h[6] = __floats2half2_rn(f1.z, f1.w);   // p3
    h[7] = __floats2half2_rn(f3.z, f3.w);   // p7
    float4* dst = isX ? ((float4*)g_xh + (size_t)z * 2097152 + 2 * (size_t)g)
                      : ((float4*)g_wh + (size_t)z * 131072 + 2 * (size_t)g);
    dst[0] = *(float4*)&h[0];
    dst[1] = *(float4*)&h[4];
}

// ---------------- Phase 1: fused QKV projection (fp16 m16n8k16, paired ktiles) ----------------
// R13-proven: 128x128 CTA tile, 8 warps, 64x32 warptile, stride 48, one sync per super.
#define SSTRH 48
#define STGH (128 * SSTRH)           // halves per matrix per ktile (6144)
#define SUPER (4 * STGH)             // halves per super-buffer (A0,A1,B0,B1)

__global__ __launch_bounds__(256, 2) void gemm_qkv(
    const float* __restrict__ bq, const float* __restrict__ bk, const float* __restrict__ bv)
{
    extern __shared__ __half smh[];  // [2 super][A0 | A1 | B0 | B1]

    const int z = blockIdx.z;
    const __half* X   = g_xh + (size_t)z * (M_TOT * E_DIM);
    const __half* W   = g_wh + (size_t)z * (E_DIM * E_DIM);
    const float* bias = (z == 0) ? bq : (z == 1) ? bk : bv;
    __half* dst       = (z == 0) ? g_qh : (z == 1) ? g_kh : g_vh;
    const bool do_relu = (z < 2);

    const int m0 = blockIdx.y * 128;
    const int n0 = blockIdx.x * 128;
    const int t = threadIdx.x;
    const int lane = t & 31, warp = t >> 5;
    const int wm = (warp & 1) * 64, wn = (warp >> 1) * 32;
    const int gid = lane >> 2, tig = lane & 3;

    const int lr4 = t >> 2;          // 0..63
    const int seg = (t & 3) * 8;     // halves offset: 0,8,16,24
    const __half* Ag = X + (size_t)m0 * E_DIM;
    const __half* Bg = W + (size_t)n0 * E_DIM;

    float acc[4][4][4];
#pragma unroll
    for (int i = 0; i < 4; ++i)
#pragma unroll
        for (int j = 0; j < 4; ++j)
#pragma unroll
            for (int e = 0; e < 4; ++e) acc[i][j][e] = 0.f;

    // stage super j = ktiles 2j, 2j+1 into buffer j&1
    auto stage = [&](int j) {
        __half* base = smh + (j & 1) * SUPER;
#pragma unroll
        for (int sub = 0; sub < 2; ++sub) {
            const int kt = 2 * j + sub;
            __half* sA = base + sub * STGH;
            __half* sB = base + 2 * STGH + sub * STGH;
#pragma unroll
            for (int i = 0; i < 2; ++i) {
                const int row = lr4 + i * 64;
                cpa16(&sA[row * SSTRH + seg], Ag + (size_t)row * E_DIM + kt * 32 + seg);
                cpa16(&sB[row * SSTRH + seg], Bg + (size_t)row * E_DIM + kt * 32 + seg);
            }
        }
        asm volatile("cp.async.commit_group;\n");
    };

    stage(0);
#pragma unroll 1
    for (int j = 0; j < 16; ++j) {
        asm volatile("cp.async.wait_group 0;\n");   // own stage(j) complete
        __syncthreads();                            // all warps' stage(j) visible
        if (j < 15) stage(j + 1);                   // writes other buffer; overlaps compute
        const __half* base = smh + (j & 1) * SUPER;
#pragma unroll
        for (int sub = 0; sub < 2; ++sub) {
            const __half* sA = base + sub * STGH;
            const __half* sB = base + 2 * STGH + sub * STGH;
#pragma unroll
            for (int s = 0; s < 2; ++s) {
                const int kpos = s * 16 + tig * 4;
                uint2 aF[4][2];
                uint2 bF[4];
#pragma unroll
                for (int mf = 0; mf < 4; ++mf) {
                    const int r = wm + mf * 16 + gid;
                    aF[mf][0] = *(const uint2*)&sA[r * SSTRH + kpos];
                    aF[mf][1] = *(const uint2*)&sA[(r + 8) * SSTRH + kpos];
                }
#pragma unroll
                for (int nf = 0; nf < 4; ++nf) {
                    const int cb = wn + nf * 8 + gid;
                    bF[nf] = *(const uint2*)&sB[cb * SSTRH + kpos];
                }
#pragma unroll
                for (int mf = 0; mf < 4; ++mf)
#pragma unroll
                    for (int nf = 0; nf < 4; ++nf)
                        mma_f16(acc[mf][nf],
                                aF[mf][0].x, aF[mf][1].x, aF[mf][0].y, aF[mf][1].y,
                                bF[nf].x, bF[nf].y);
            }
        }
    }

    // epilogue: bias + relu + fp16 + scatter to [head][l][hd] (half2 stores)
#pragma unroll
    for (int mf = 0; mf < 4; ++mf) {
#pragma unroll
        for (int nf = 0; nf < 4; ++nf) {
            const int row = m0 + wm + mf * 16 + gid;
            const int col = n0 + wn + nf * 8 + tig * 2;   // even
            const float b0 = __ldg(&bias[col]);
            const float b1 = __ldg(&bias[col + 1]);
            const int hh = col >> 6, hd = col & 63;
#pragma unroll
            for (int half8 = 0; half8 < 2; ++half8) {
                const int r = row + half8 * 8;
                float v0 = acc[mf][nf][half8 * 2 + 0] + b0;
                float v1 = acc[mf][nf][half8 * 2 + 1] + b1;
                if (do_relu) { v0 = fmaxf(v0, 0.f); v1 = fmaxf(v1, 0.f); }
                const int l = r >> 2, bb = r & 3;
                const int head = bb * H_DIM + hh;
                *(__half2*)&dst[((size_t)head << 18) + ((size_t)l << 6) + (size_t)hd] =
                    __floats2half2_rn(v0, v1);
            }
        }
    }
}

// ---------------- Phase 2: kv = k_^T v, fp16 inputs, register-prefetch, tf32 MMA ----------------
// grid (NH, KCH): 256 l per chunk, 8 tiles of 32.
__global__ __launch_bounds__(256, 2) void kv2() {
    __shared__ float Ks[32 * 136];   // [l][128 scaled d], stride 136
    __shared__ float Vs[32 * 72];    // [l][64 m], stride 72

    const int h = blockIdx.x, ch = blockIdx.y;
    const int t = threadIdx.x, lane = t & 31, warp = t >> 5;
    const int wm = (warp >> 1) * 32, wn = (warp & 1) * 32;
    const int gid = lane >> 2, tig = lane & 3;

    float acc[2][4][4];
#pragma unroll
    for (int mf = 0; mf < 2; ++mf)
#pragma unroll
        for (int nf = 0; nf < 4; ++nf)
#pragma unroll
            for (int e = 0; e < 4; ++e) acc[mf][nf][e] = 0.f;
    float ksacc = 0.f;

    const __half* kp = g_kh + ((size_t)h << 18);
    const __half* vp = g_vh + ((size_t)h << 18);
    const int ll = t >> 3;
    const int f = (t & 7) * 8;
    const int ch0 = ch * 256;
    const int kd = t & 127;          // ksum: d index
    const int kj0 = (t >> 7) * 16;   // ksum: j half

    uint4 kraw, vraw;   // 8 halves each
    {
        const size_t b = (size_t)(ch0 + ll) * 64 + f;
        kraw = *(const uint4*)(kp + b);
        vraw = *(const uint4*)(vp + b);
    }

#pragma unroll 1
    for (int it = 0; it < 8; ++it) {
        {
            const int l = ch0 + it * 32 + ll;
            float s, c;
            sincosf(ANG_C * (float)(l + 1), &s, &c);
            const __half2* kh2 = (const __half2*)&kraw;
            const __half2* vh2 = (const __half2*)&vraw;
            float kf[8], vf[8];
#pragma unroll
            for (int j = 0; j < 4; ++j) {
                const float2 kj = __half22float2(kh2[j]);
                const float2 vj = __half22float2(vh2[j]);
                kf[2 * j] = kj.x; kf[2 * j + 1] = kj.y;
                vf[2 * j] = vj.x; vf[2 * j + 1] = vj.y;
            }
#pragma unroll
            for (int j = 0; j < 8; ++j) {
                Ks[ll * 136 + f + j]      = ftf(kf[j] * s);
                Ks[ll * 136 + 64 + f + j] = ftf(kf[j] * c);
                Vs[ll * 72 + f + j]       = ftf(vf[j]);
            }
        }
        __syncthreads();
        if (it < 7) {
            const size_t b = (size_t)(ch0 + (it + 1) * 32 + ll) * 64 + f;
            kraw = *(const uint4*)(kp + b);
            vraw = *(const uint4*)(vp + b);
        }
        // ksum split across all 256 threads: 16 rows each
#pragma unroll
        for (int j = 0; j < 16; ++j) ksacc += Ks[(kj0 + j) * 136 + kd];
#pragma unroll
        for (int k8 = 0; k8 < 4; ++k8) {
            const int kk = k8 * 8;
            unsigned af[2][4], bf[4][2];
#pragma unroll
            for (int mf = 0; mf < 2; ++mf) {
                const int r = wm + mf * 16 + gid;
                af[mf][0] = __float_as_uint(Ks[(kk + tig) * 136 + r]);
                af[mf][1] = __float_as_uint(Ks[(kk + tig) * 136 + r + 8]);
                af[mf][2] = __float_as_uint(Ks[(kk + tig + 4) * 136 + r]);
                af[mf][3] = __float_as_uint(Ks[(kk + tig + 4) * 136 + r + 8]);
            }
#pragma unroll
            for (int nf = 0; nf < 4; ++nf) {
                const int cb = wn + nf * 8 + gid;
                bf[nf][0] = __float_as_uint(Vs[(kk + tig) * 72 + cb]);
                bf[nf][1] = __float_as_uint(Vs[(kk + tig + 4) * 72 + cb]);
            }
#pragma unroll
            for (int mf = 0; mf < 2; ++mf)
#pragma unroll
                for (int nf = 0; nf < 4; ++nf)
                    mma_tf32(acc[mf][nf], af[mf][0], af[mf][1], af[mf][2], af[mf][3],
                             bf[nf][0], bf[nf][1]);
        }
        __syncthreads();
    }

    float* outp = g_kv_part + (size_t)(h * KCH + ch) * 8192;
#pragma unroll
    for (int mf = 0; mf < 2; ++mf) {
#pragma unroll
        for (int nf = 0; nf < 4; ++nf) {
            const int row = wm + mf * 16 + gid;
            const int col = wn + nf * 8 + tig * 2;
            *(float2*)&outp[row * 64 + col] = make_float2(acc[mf][nf][0], acc[mf][nf][1]);
            *(float2*)&outp[(row + 8) * 64 + col] = make_float2(acc[mf][nf][2], acc[mf][nf][3]);
        }
    }
    g_ks_part[(size_t)(h * KCH + ch) * 256 + t] = ksacc;
}

// ---------------- Phase 2b: reduce partials ----------------
// grid (NH, 9): y<8 -> 1024 kv elements each; y==8 -> ksum (128 lanes, 2 halves x KCH)
__global__ __launch_bounds__(256) void reduce_kv() {
    const int h = blockIdx.x, seg = blockIdx.y, t = threadIdx.x;
    if (seg < 8) {
        const int base = seg * 1024;
#pragma unroll
        for (int r = 0; r < 4; ++r) {
            const int i = base + r * 256 + t;
            float s = 0.f;
#pragma unroll
            for (int p = 0; p < KCH; ++p)
                s += g_kv_part[(size_t)(h * KCH + p) * 8192 + i];
            g_kv[(size_t)h * 8192 + i] = s;
        }
    } else if (t < 128) {
        float s = 0.f;
#pragma unroll
        for (int p = 0; p < KCH; ++p) {
            const float* sp = g_ks_part + (size_t)(h * KCH + p) * 256;
            s += sp[t] + sp[128 + t];
        }
        g_ks[h * 128 + t] = s;
    }
}

// ---------------- Phase 3: out = (q_ @ kv) * z, fp16 m16n8k16 ----------------
#define OSTR 144

__global__ __launch_bounds__(256, 2) void out2(float* __restrict__ out) {
    extern __shared__ char sm3raw[];
    __half* KVh  = (__half*)sm3raw;                       // 64*144*2  = 18432 B
    __half* Qh   = (__half*)(sm3raw + 18432);             // 128*144*2 = 36864 B
    float*  kssP = (float*)(sm3raw + 18432 + 36864);      // 128 floats (permuted order)
    float*  zden = kssP + 128;                            // 128 floats
    float*  smemF = (float*)(sm3raw + 18432);             // transient: overlaps Qh (32768 B)

    const int h = blockIdx.x, ch = blockIdx.y;
    const int t = threadIdx.x, lane = t & 31, warp = t >> 5;
    const int wm = (warp >> 1) * 32, wn = (warp & 1) * 32;
    const int gid = lane >> 2, tig = lane & 3;

    // 1. coalesced load of kv into fp32 scratch, kss permuted
    for (int i = t; i < 8192; i += 256) smemF[i] = g_kv[(size_t)h * 8192 + i];
    if (t < 128) kssP[permpos(t)] = g_ks[h * 128 + t];
    __syncthreads();

    // 2. transpose + permute + fp16: KVh[m][perm(d)] = kv[d][m]
    {
        const int m = t & 63, q4 = t >> 6;
#pragma unroll
        for (int dd = 0; dd < 32; ++dd) {
            const int d = q4 * 32 + dd;
            KVh[m * OSTR + permpos(d)] = __float2half(smemF[d * 64 + m]);
        }
    }
    __syncthreads();   // smemF dead; Qh region reused below

    const __half* qp = g_qh + ((size_t)h << 18);
    const int bb = h >> 4, hh = h & 15;

#pragma unroll 1
    for (int it = 0; it < 4; ++it) {
        const int l0 = ch * 512 + it * 128;
        // 2a. stage q_ (sin|cos scaled), fp16 pair-permuted
        {
            const int lq = t >> 1;
            const int fq = (t & 1) * 32;
            const int l = l0 + lq;
            float s, c;
            sincosf(ANG_C * (float)(l + 1), &s, &c);
            const __half* qrow = qp + (size_t)l * 64 + fq;
            const uint4 qr0 = *(const uint4*)(qrow + 0);    // halves 0..7
            const uint4 qr1 = *(const uint4*)(qrow + 8);    // halves 8..15
            const uint4 qr2 = *(const uint4*)(qrow + 16);   // halves 16..23
            const uint4 qr3 = *(const uint4*)(qrow + 24);   // halves 24..31
            float qvall[32];
#pragma unroll
            for (int j = 0; j < 4; ++j) {
                const float2 a  = __half22float2(((const __half2*)&qr0)[j]);
                qvall[2 * j] = a.x;       qvall[2 * j + 1] = a.y;
                const float2 b2 = __half22float2(((const __half2*)&qr1)[j]);
                qvall[8 + 2 * j] = b2.x;  qvall[9 + 2 * j] = b2.y;
                const float2 c2 = __half22float2(((const __half2*)&qr2)[j]);
                qvall[16 + 2 * j] = c2.x; qvall[17 + 2 * j] = c2.y;
                const float2 d2 = __half22float2(((const __half2*)&qr3)[j]);
                qvall[24 + 2 * j] = d2.x; qvall[25 + 2 * j] = d2.y;
            }
#pragma unroll
            for (int g2 = 0; g2 < 2; ++g2) {
                const float* qv = &qvall[g2 * 16];
                __half2 hs[8], hc[8];
#pragma unroll
                for (int j = 0; j < 4; ++j) {
                    hs[2 * j]     = __floats2half2_rn(qv[2 * j] * s, qv[2 * j + 1] * s);
                    hs[2 * j + 1] = __floats2half2_rn(qv[8 + 2 * j] * s, qv[9 + 2 * j] * s);
                    hc[2 * j]     = __floats2half2_rn(qv[2 * j] * c, qv[2 * j + 1] * c);
                    hc[2 * j + 1] = __floats2half2_rn(qv[8 + 2 * j] * c, qv[9 + 2 * j] * c);
                }
                const int baseS = lq * OSTR + fq + g2 * 16;
                const int baseC = lq * OSTR + 64 + fq + g2 * 16;
                *(float4*)&Qh[baseS]     = *(float4*)&hs[0];
                *(float4*)&Qh[baseS + 8] = *(float4*)&hs[4];
                *(float4*)&Qh[baseC]     = *(float4*)&hc[0];
                *(float4*)&Qh[baseC + 8] = *(float4*)&hc[4];
            }
        }
        __syncthreads();
        // 2b. z denominator
        {
            const int lz = t >> 1;
            const int dh = (t & 1) * 64;
            float p = 0.f;
#pragma unroll
            for (int j = 0; j < 32; ++j) {
                const __half2 hv = *(const __half2*)&Qh[lz * OSTR + dh + 2 * j];
                const float2 fv = __half22float2(hv);
                p += fv.x * kssP[dh + 2 * j] + fv.y * kssP[dh + 2 * j + 1];
            }
            p += __shfl_xor_sync(0xffffffffu, p, 1);
            if ((t & 1) == 0) zden[lz] = 1.0f / fmaxf(p, EPS_F);
        }
        __syncthreads();

        float acc[2][4][4];
#pragma unroll
        for (int mf = 0; mf < 2; ++mf)
#pragma unroll
            for (int nf = 0; nf < 4; ++nf)
#pragma unroll
                for (int e = 0; e < 4; ++e) acc[mf][nf][e] = 0.f;

#pragma unroll
        for (int k16 = 0; k16 < 8; ++k16) {
            const int kpos = k16 * 16 + tig * 4;
            uint2 aF[2][2];
            uint2 bF[4];
#pragma unroll
            for (int mf = 0; mf < 2; ++mf) {
                const int r = wm + mf * 16 + gid;
                aF[mf][0] = *(const uint2*)&Qh[r * OSTR + kpos];
                aF[mf][1] = *(const uint2*)&Qh[(r + 8) * OSTR + kpos];
            }
#pragma unroll
            for (int nf = 0; nf < 4; ++nf) {
                const int cb = wn + nf * 8 + gid;
                bF[nf] = *(const uint2*)&KVh[cb * OSTR + kpos];
            }
#pragma unroll
            for (int mf = 0; mf < 2; ++mf)
#pragma unroll
                for (int nf = 0; nf < 4; ++nf)
                    mma_f16(acc[mf][nf],
                            aF[mf][0].x, aF[mf][1].x, aF[mf][0].y, aF[mf][1].y,
                            bF[nf].x, bF[nf].y);
        }

#pragma unroll
        for (int mf = 0; mf < 2; ++mf) {
#pragma unroll
            for (int nf = 0; nf < 4; ++nf) {
                const int rl = wm + mf * 16 + gid;
                const int col = hh * 64 + wn + nf * 8 + tig * 2;
                const float z0 = zden[rl];
                const float z1 = zden[rl + 8];
                const int l_a = l0 + rl;
                const int l_b = l_a + 8;
                *(float2*)&out[((size_t)l_a * B_DIM + bb) * E_DIM + col] =
                    make_float2(acc[mf][nf][0] * z0, acc[mf][nf][1] * z0);
                *(float2*)&out[((size_t)l_b * B_DIM + bb) * E_DIM + col] =
                    make_float2(acc[mf][nf][2] * z1, acc[mf][nf][3] * z1);
            }
        }
        __syncthreads();
    }
}

// ---------------- launch ----------------
extern "C" void kernel_launch(void* const* d_in, const int* in_sizes, int n_in,
                              void* d_out, int out_size) {
    const float* q  = (const float*)d_in[0];
    const float* k  = (const float*)d_in[1];
    const float* v  = (const float*)d_in[2];
    const float* Wq = (const float*)d_in[3];
    const float* bq = (const float*)d_in[4];
    const float* Wk = (const float*)d_in[5];
    const float* bk = (const float*)d_in[6];
    const float* Wv = (const float*)d_in[7];
    const float* bv = (const float*)d_in[8];
    float* out = (float*)d_out;

    const int smem1 = 2 * SUPER * 2;                        // 98304 B
    const int smem3 = 18432 + 36864 + 512 + 512;            // 56320 B
    cudaFuncSetAttribute(gemm_qkv, cudaFuncAttributeMaxDynamicSharedMemorySize, smem1);
    cudaFuncSetAttribute(out2, cudaFuncAttributeMaxDynamicSharedMemorySize, smem3);

    preround_xw<<<dim3(4352, 3), 256>>>((const float4*)q, (const float4*)k, (const float4*)v,
                                        (const float4*)Wq, (const float4*)Wk, (const float4*)Wv);
    dim3 g1(E_DIM / 128, M_TOT / 128, 3);   // (8, 128, 3)
    gemm_qkv<<<g1, 256, smem1>>>(bq, bk, bv);
    kv2<<<dim3(NH, KCH), 256>>>();
    reduce_kv<<<dim3(NH, 9), 256>>>();
    out2<<<dim3(NH, OCH), 256, smem3>>>(out);
}

// round 16
// speedup vs baseline: 1.3105x; 1.0944x over previous
#include <cuda_runtime.h>
#include <cuda_fp16.h>
#include <cstdint>

#define L_DIM 4096
#define B_DIM 4
#define E_DIM 1024
#define H_DIM 16
#define HD 64
#define NH 64            // B*H
#define M_TOT 16384      // L*B
#define EPS_F 1e-4f
#define ANG_C 3.83495196971410283e-4f   // (pi/2)/4096
#define KCH 16           // kv2 L-chunks
#define OCH 8            // out2 L-chunks

// ---------------- scratch (device globals; no allocs allowed) ----------------
__device__ __half g_qh[NH * L_DIM * HD];               // relu(Q), fp16, head-major
__device__ __half g_kh[NH * L_DIM * HD];               // relu(K), fp16
__device__ __half g_vh[NH * L_DIM * HD];               // V, fp16
__device__ __half g_xh[3 * M_TOT * E_DIM];             // fp16, pair-permuted X (q,k,v)
__device__ __half g_wh[3 * E_DIM * E_DIM];             // fp16, pair-permuted W (q,k,v)
__device__ float g_kv_part[NH * KCH * 2 * HD * HD];    // per-chunk partial kv [d128][m64]
__device__ float g_ks_part[NH * KCH * 256];            // per-chunk partial ksum (2 halves x 128)
__device__ float g_kv[NH * 2 * HD * HD];               // reduced kv
__device__ float g_ks[NH * 2 * HD];                    // reduced ksum

__device__ __forceinline__ unsigned f2tf32(float x) {
    unsigned r;
    asm("cvt.rna.tf32.f32 %0, %1;" : "=r"(r) : "f"(x));
    return r;
}
__device__ __forceinline__ float ftf(float x) { return __uint_as_float(f2tf32(x)); }

// position of scalar d within a pair-permuted 16-element group layout
__device__ __forceinline__ int permpos(int d) {
    const int g = d >> 4, j = (d >> 1) & 7, o = d & 1;
    const int jp = (j < 4) ? (2 * j) : (2 * (j - 4) + 1);
    return (g << 4) + (jp << 1) + o;
}

__device__ __forceinline__ void mma_f16(float c[4],
                                        unsigned a0, unsigned a1, unsigned a2, unsigned a3,
                                        unsigned b0, unsigned b1) {
    asm volatile(
        "mma.sync.aligned.m16n8k16.row.col.f32.f16.f16.f32 "
        "{%0,%1,%2,%3}, {%4,%5,%6,%7}, {%8,%9}, {%0,%1,%2,%3};\n"
        : "+f"(c[0]), "+f"(c[1]), "+f"(c[2]), "+f"(c[3])
        : "r"(a0), "r"(a1), "r"(a2), "r"(a3), "r"(b0), "r"(b1));
}

__device__ __forceinline__ void ldsm_x4_t(unsigned &r0, unsigned &r1, unsigned &r2, unsigned &r3,
                                          const __half* p) {
    unsigned a = (unsigned)__cvta_generic_to_shared(p);
    asm volatile("ldmatrix.sync.aligned.m8n8.x4.trans.shared.b16 {%0,%1,%2,%3}, [%4];"
                 : "=r"(r0), "=r"(r1), "=r"(r2), "=r"(r3) : "r"(a));
}

__device__ __forceinline__ void cpa16(void* dst, const void* src) {
    unsigned d = (unsigned)__cvta_generic_to_shared(dst);
    asm volatile("cp.async.cg.shared.global [%0], [%1], 16;\n" :: "r"(d), "l"(src));
}

// ---------------- Phase 0: fp16-round + pair-permute X and W (fused) ----------------
__global__ __launch_bounds__(256) void preround_xw(
    const float4* __restrict__ xq, const float4* __restrict__ xk, const float4* __restrict__ xv,
    const float4* __restrict__ wq, const float4* __restrict__ wk, const float4* __restrict__ wv)
{
    const int bx = blockIdx.x;
    const int z = blockIdx.y;
    const bool isX = (bx < 4096);
    const int g = (isX ? bx : (bx - 4096)) * 256 + threadIdx.x;
    const float4* src = isX ? ((z == 0) ? xq : (z == 1) ? xk : xv)
                            : ((z == 0) ? wq : (z == 1) ? wk : wv);
    const float4 f0 = src[4 * g + 0];
    const float4 f1 = src[4 * g + 1];
    const float4 f2 = src[4 * g + 2];
    const float4 f3 = src[4 * g + 3];
    __half2 h[8];
    h[0] = __floats2half2_rn(f0.x, f0.y);   // p0
    h[1] = __floats2half2_rn(f2.x, f2.y);   // p4
    h[2] = __floats2half2_rn(f0.z, f0.w);   // p1
    h[3] = __floats2half2_rn(f2.z, f2.w);   // p5
    h[4] = __floats2half2_rn(f1.x, f1.y);   // p2
    h[5] = __floats2half2_rn(f3.x, f3.y);   // p6
    h[6] = __floats2half2_rn(f1.z, f1.w);   // p3
    h[7] = __floats2half2_rn(f3.z, f3.w);   // p7
    float4* dst = isX ? ((float4*)g_xh + (size_t)z * 2097152 + 2 * (size_t)g)
                      : ((float4*)g_wh + (size_t)z * 131072 + 2 * (size_t)g);
    dst[0] = *(float4*)&h[0];
    dst[1] = *(float4*)&h[4];
}

// ---------------- Phase 1: fused QKV projection (fp16 m16n8k16, paired ktiles) ----------------
// R13-proven: 128x128 CTA tile, 8 warps, 64x32 warptile, stride 48, one sync per super.
#define SSTRH 48
#define STGH (128 * SSTRH)           // halves per matrix per ktile (6144)
#define SUPER (4 * STGH)             // halves per super-buffer (A0,A1,B0,B1)

__global__ __launch_bounds__(256, 2) void gemm_qkv(
    const float* __restrict__ bq, const float* __restrict__ bk, const float* __restrict__ bv)
{
    extern __shared__ __half smh[];  // [2 super][A0 | A1 | B0 | B1]

    const int z = blockIdx.z;
    const __half* X   = g_xh + (size_t)z * (M_TOT * E_DIM);
    const __half* W   = g_wh + (size_t)z * (E_DIM * E_DIM);
    const float* bias = (z == 0) ? bq : (z == 1) ? bk : bv;
    __half* dst       = (z == 0) ? g_qh : (z == 1) ? g_kh : g_vh;
    const bool do_relu = (z < 2);

    const int m0 = blockIdx.y * 128;
    const int n0 = blockIdx.x * 128;
    const int t = threadIdx.x;
    const int lane = t & 31, warp = t >> 5;
    const int wm = (warp & 1) * 64, wn = (warp >> 1) * 32;
    const int gid = lane >> 2, tig = lane & 3;

    const int lr4 = t >> 2;          // 0..63
    const int seg = (t & 3) * 8;     // halves offset: 0,8,16,24
    const __half* Ag = X + (size_t)m0 * E_DIM;
    const __half* Bg = W + (size_t)n0 * E_DIM;

    float acc[4][4][4];
#pragma unroll
    for (int i = 0; i < 4; ++i)
#pragma unroll
        for (int j = 0; j < 4; ++j)
#pragma unroll
            for (int e = 0; e < 4; ++e) acc[i][j][e] = 0.f;

    // stage super j = ktiles 2j, 2j+1 into buffer j&1
    auto stage = [&](int j) {
        __half* base = smh + (j & 1) * SUPER;
#pragma unroll
        for (int sub = 0; sub < 2; ++sub) {
            const int kt = 2 * j + sub;
            __half* sA = base + sub * STGH;
            __half* sB = base + 2 * STGH + sub * STGH;
#pragma unroll
            for (int i = 0; i < 2; ++i) {
                const int row = lr4 + i * 64;
                cpa16(&sA[row * SSTRH + seg], Ag + (size_t)row * E_DIM + kt * 32 + seg);
                cpa16(&sB[row * SSTRH + seg], Bg + (size_t)row * E_DIM + kt * 32 + seg);
            }
        }
        asm volatile("cp.async.commit_group;\n");
    };

    stage(0);
#pragma unroll 1
    for (int j = 0; j < 16; ++j) {
        asm volatile("cp.async.wait_group 0;\n");   // own stage(j) complete
        __syncthreads();                            // all warps' stage(j) visible
        if (j < 15) stage(j + 1);                   // writes other buffer; overlaps compute
        const __half* base = smh + (j & 1) * SUPER;
#pragma unroll
        for (int sub = 0; sub < 2; ++sub) {
            const __half* sA = base + sub * STGH;
            const __half* sB = base + 2 * STGH + sub * STGH;
#pragma unroll
            for (int s = 0; s < 2; ++s) {
                const int kpos = s * 16 + tig * 4;
                uint2 aF[4][2];
                uint2 bF[4];
#pragma unroll
                for (int mf = 0; mf < 4; ++mf) {
                    const int r = wm + mf * 16 + gid;
                    aF[mf][0] = *(const uint2*)&sA[r * SSTRH + kpos];
                    aF[mf][1] = *(const uint2*)&sA[(r + 8) * SSTRH + kpos];
                }
#pragma unroll
                for (int nf = 0; nf < 4; ++nf) {
                    const int cb = wn + nf * 8 + gid;
                    bF[nf] = *(const uint2*)&sB[cb * SSTRH + kpos];
                }
#pragma unroll
                for (int mf = 0; mf < 4; ++mf)
#pragma unroll
                    for (int nf = 0; nf < 4; ++nf)
                        mma_f16(acc[mf][nf],
                                aF[mf][0].x, aF[mf][1].x, aF[mf][0].y, aF[mf][1].y,
                                bF[nf].x, bF[nf].y);
            }
        }
    }

    // epilogue: bias + relu + fp16 + scatter to [head][l][hd] (half2 stores)
#pragma unroll
    for (int mf = 0; mf < 4; ++mf) {
#pragma unroll
        for (int nf = 0; nf < 4; ++nf) {
            const int row = m0 + wm + mf * 16 + gid;
            const int col = n0 + wn + nf * 8 + tig * 2;   // even
            const float b0 = __ldg(&bias[col]);
            const float b1 = __ldg(&bias[col + 1]);
            const int hh = col >> 6, hd = col & 63;
#pragma unroll
            for (int half8 = 0; half8 < 2; ++half8) {
                const int r = row + half8 * 8;
                float v0 = acc[mf][nf][half8 * 2 + 0] + b0;
                float v1 = acc[mf][nf][half8 * 2 + 1] + b1;
                if (do_relu) { v0 = fmaxf(v0, 0.f); v1 = fmaxf(v1, 0.f); }
                const int l = r >> 2, bb = r & 3;
                const int head = bb * H_DIM + hh;
                *(__half2*)&dst[((size_t)head << 18) + ((size_t)l << 6) + (size_t)hd] =
                    __floats2half2_rn(v0, v1);
            }
        }
    }
}

// ---------------- Phase 2: kv = k_^T v, fp16 staging + ldmatrix.trans + fp16 MMA ----------------
// grid (NH, KCH): 256 l per chunk, 8 tiles of 32.
// D[d 128][m 64]: A = k_ (m-dim=d, k-dim=l) from Ks[l][d]; B = v (n-dim=m) from Vs[l][m].
__global__ __launch_bounds__(256, 2) void kv2() {
    __shared__ __align__(16) __half Ks[32 * 136];   // [l][128 scaled d], stride 136 halves
    __shared__ __align__(16) __half Vs[32 * 72];    // [l][64 m], stride 72 halves

    const int h = blockIdx.x, ch = blockIdx.y;
    const int t = threadIdx.x, lane = t & 31, warp = t >> 5;
    const int wm = (warp >> 1) * 32, wn = (warp & 1) * 32;

    // ldmatrix address offsets (derived: A .trans of [k][m]; B .trans of [k][n])
    const int lane7 = lane & 7;
    const int arow = ((lane & 16) ? 8 : 0) + lane7;   // A: k-row within k16
    const int acol = (lane & 8) ? 8 : 0;              // A: m(d)-col offset
    const int brow = ((lane & 8) ? 8 : 0) + lane7;    // B: k-row within k16
    const int bcol = (lane & 16) ? 8 : 0;             // B: n(m)-col offset

    float acc[2][4][4];
#pragma unroll
    for (int mf = 0; mf < 2; ++mf)
#pragma unroll
        for (int nf = 0; nf < 4; ++nf)
#pragma unroll
            for (int e = 0; e < 4; ++e) acc[mf][nf][e] = 0.f;
    float ksacc = 0.f;

    const __half* kp = g_kh + ((size_t)h << 18);
    const __half* vp = g_vh + ((size_t)h << 18);
    const int ll = t >> 3;
    const int f = (t & 7) * 8;
    const int ch0 = ch * 256;
    const int kd = t & 127;          // ksum: d index
    const int kj0 = (t >> 7) * 16;   // ksum: j half

    uint4 kraw, vraw;   // 8 halves each
    {
        const size_t b = (size_t)(ch0 + ll) * 64 + f;
        kraw = *(const uint4*)(kp + b);
        vraw = *(const uint4*)(vp + b);
    }

#pragma unroll 1
    for (int it = 0; it < 8; ++it) {
        {
            const int l = ch0 + it * 32 + ll;
            float s, c;
            sincosf(ANG_C * (float)(l + 1), &s, &c);
            const __half2* kh2 = (const __half2*)&kraw;
            __half2 hs[4], hc[4];
#pragma unroll
            for (int j = 0; j < 4; ++j) {
                const float2 kj = __half22float2(kh2[j]);
                hs[j] = __floats2half2_rn(kj.x * s, kj.y * s);
                hc[j] = __floats2half2_rn(kj.x * c, kj.y * c);
            }
            *(uint4*)&Ks[ll * 136 + f]      = *(uint4*)&hs[0];
            *(uint4*)&Ks[ll * 136 + 64 + f] = *(uint4*)&hc[0];
            *(uint4*)&Vs[ll * 72 + f]       = vraw;   // v stays exact fp16
        }
        __syncthreads();
        if (it < 7) {
            const size_t b = (size_t)(ch0 + (it + 1) * 32 + ll) * 64 + f;
            kraw = *(const uint4*)(kp + b);
            vraw = *(const uint4*)(vp + b);
        }
        // ksum split across all 256 threads: 16 rows each
#pragma unroll
        for (int j = 0; j < 16; ++j) ksacc += __half2float(Ks[(kj0 + j) * 136 + kd]);
#pragma unroll
        for (int ks = 0; ks < 2; ++ks) {
            const int kr = ks * 16;
            unsigned a[2][4], b[2][4];
#pragma unroll
            for (int mf = 0; mf < 2; ++mf)
                ldsm_x4_t(a[mf][0], a[mf][1], a[mf][2], a[mf][3],
                          &Ks[(kr + arow) * 136 + wm + mf * 16 + acol]);
#pragma unroll
            for (int np = 0; np < 2; ++np)
                ldsm_x4_t(b[np][0], b[np][1], b[np][2], b[np][3],
                          &Vs[(kr + brow) * 72 + wn + np * 16 + bcol]);
#pragma unroll
            for (int mf = 0; mf < 2; ++mf)
#pragma unroll
                for (int nf = 0; nf < 4; ++nf) {
                    const int np = nf >> 1, w2 = (nf & 1) * 2;
                    mma_f16(acc[mf][nf], a[mf][0], a[mf][1], a[mf][2], a[mf][3],
                            b[np][w2], b[np][w2 + 1]);
                }
        }
        __syncthreads();
    }

    const int gid = lane >> 2, tig = lane & 3;
    float* outp = g_kv_part + (size_t)(h * KCH + ch) * 8192;
#pragma unroll
    for (int mf = 0; mf < 2; ++mf) {
#pragma unroll
        for (int nf = 0; nf < 4; ++nf) {
            const int row = wm + mf * 16 + gid;
            const int col = wn + nf * 8 + tig * 2;
            *(float2*)&outp[row * 64 + col] = make_float2(acc[mf][nf][0], acc[mf][nf][1]);
            *(float2*)&outp[(row + 8) * 64 + col] = make_float2(acc[mf][nf][2], acc[mf][nf][3]);
        }
    }
    g_ks_part[(size_t)(h * KCH + ch) * 256 + t] = ksacc;
}

// ---------------- Phase 2b: reduce partials ----------------
// grid (NH, 9): y<8 -> 1024 kv elements each; y==8 -> ksum (128 lanes, 2 halves x KCH)
__global__ __launch_bounds__(256) void reduce_kv() {
    const int h = blockIdx.x, seg = blockIdx.y, t = threadIdx.x;
    if (seg < 8) {
        const int base = seg * 1024;
#pragma unroll
        for (int r = 0; r < 4; ++r) {
            const int i = base + r * 256 + t;
            float s = 0.f;
#pragma unroll
            for (int p = 0; p < KCH; ++p)
                s += g_kv_part[(size_t)(h * KCH + p) * 8192 + i];
            g_kv[(size_t)h * 8192 + i] = s;
        }
    } else if (t < 128) {
        float s = 0.f;
#pragma unroll
        for (int p = 0; p < KCH; ++p) {
            const float* sp = g_ks_part + (size_t)(h * KCH + p) * 256;
            s += sp[t] + sp[128 + t];
        }
        g_ks[h * 128 + t] = s;
    }
}

// ---------------- Phase 3: out = (q_ @ kv) * z, fp16 m16n8k16 ----------------
#define OSTR 144

__global__ __launch_bounds__(256, 2) void out2(float* __restrict__ out) {
    extern __shared__ char sm3raw[];
    __half* KVh  = (__half*)sm3raw;                       // 64*144*2  = 18432 B
    __half* Qh   = (__half*)(sm3raw + 18432);             // 128*144*2 = 36864 B
    float*  kssP = (float*)(sm3raw + 18432 + 36864);      // 128 floats (permuted order)
    float*  zden = kssP + 128;                            // 128 floats
    float*  smemF = (float*)(sm3raw + 18432);             // transient: overlaps Qh (32768 B)

    const int h = blockIdx.x, ch = blockIdx.y;
    const int t = threadIdx.x, lane = t & 31, warp = t >> 5;
    const int wm = (warp >> 1) * 32, wn = (warp & 1) * 32;
    const int gid = lane >> 2, tig = lane & 3;

    // 1. coalesced load of kv into fp32 scratch, kss permuted
    for (int i = t; i < 8192; i += 256) smemF[i] = g_kv[(size_t)h * 8192 + i];
    if (t < 128) kssP[permpos(t)] = g_ks[h * 128 + t];
    __syncthreads();

    // 2. transpose + permute + fp16: KVh[m][perm(d)] = kv[d][m]
    {
        const int m = t & 63, q4 = t >> 6;
#pragma unroll
        for (int dd = 0; dd < 32; ++dd) {
            const int d = q4 * 32 + dd;
            KVh[m * OSTR + permpos(d)] = __float2half(smemF[d * 64 + m]);
        }
    }
    __syncthreads();   // smemF dead; Qh region reused below

    const __half* qp = g_qh + ((size_t)h << 18);
    const int bb = h >> 4, hh = h & 15;

#pragma unroll 1
    for (int it = 0; it < 4; ++it) {
        const int l0 = ch * 512 + it * 128;
        // 2a. stage q_ (sin|cos scaled), fp16 pair-permuted
        {
            const int lq = t >> 1;
            const int fq = (t & 1) * 32;
            const int l = l0 + lq;
            float s, c;
            sincosf(ANG_C * (float)(l + 1), &s, &c);
            const __half* qrow = qp + (size_t)l * 64 + fq;
            const uint4 qr0 = *(const uint4*)(qrow + 0);    // halves 0..7
            const uint4 qr1 = *(const uint4*)(qrow + 8);    // halves 8..15
            const uint4 qr2 = *(const uint4*)(qrow + 16);   // halves 16..23
            const uint4 qr3 = *(const uint4*)(qrow + 24);   // halves 24..31
            float qvall[32];
#pragma unroll
            for (int j = 0; j < 4; ++j) {
                const float2 a  = __half22float2(((const __half2*)&qr0)[j]);
                qvall[2 * j] = a.x;       qvall[2 * j + 1] = a.y;
                const float2 b2 = __half22float2(((const __half2*)&qr1)[j]);
                qvall[8 + 2 * j] = b2.x;  qvall[9 + 2 * j] = b2.y;
                const float2 c2 = __half22float2(((const __half2*)&qr2)[j]);
                qvall[16 + 2 * j] = c2.x; qvall[17 + 2 * j] = c2.y;
                const float2 d2 = __half22float2(((const __half2*)&qr3)[j]);
                qvall[24 + 2 * j] = d2.x; qvall[25 + 2 * j] = d2.y;
            }
#pragma unroll
            for (int g2 = 0; g2 < 2; ++g2) {
                const float* qv = &qvall[g2 * 16];
                __half2 hs[8], hc[8];
#pragma unroll
                for (int j = 0; j < 4; ++j) {
                    hs[2 * j]     = __floats2half2_rn(qv[2 * j] * s, qv[2 * j + 1] * s);
                    hs[2 * j + 1] = __floats2half2_rn(qv[8 + 2 * j] * s, qv[9 + 2 * j] * s);
                    hc[2 * j]     = __floats2half2_rn(qv[2 * j] * c, qv[2 * j + 1] * c);
                    hc[2 * j + 1] = __floats2half2_rn(qv[8 + 2 * j] * c, qv[9 + 2 * j] * c);
                }
                const int baseS = lq * OSTR + fq + g2 * 16;
                const int baseC = lq * OSTR + 64 + fq + g2 * 16;
                *(float4*)&Qh[baseS]     = *(float4*)&hs[0];
                *(float4*)&Qh[baseS + 8] = *(float4*)&hs[4];
                *(float4*)&Qh[baseC]     = *(float4*)&hc[0];
                *(float4*)&Qh[baseC + 8] = *(float4*)&hc[4];
            }
        }
        __syncthreads();
        // 2b. z denominator
        {
            const int lz = t >> 1;
            const int dh = (t & 1) * 64;
            float p = 0.f;
#pragma unroll
            for (int j = 0; j < 32; ++j) {
                const __half2 hv = *(const __half2*)&Qh[lz * OSTR + dh + 2 * j];
                const float2 fv = __half22float2(hv);
                p += fv.x * kssP[dh + 2 * j] + fv.y * kssP[dh + 2 * j + 1];
            }
            p += __shfl_xor_sync(0xffffffffu, p, 1);
            if ((t & 1) == 0) zden[lz] = 1.0f / fmaxf(p, EPS_F);
        }
        __syncthreads();

        float acc[2][4][4];
#pragma unroll
        for (int mf = 0; mf < 2; ++mf)
#pragma unroll
            for (int nf = 0; nf < 4; ++nf)
#pragma unroll
                for (int e = 0; e < 4; ++e) acc[mf][nf][e] = 0.f;

#pragma unroll
        for (int k16 = 0; k16 < 8; ++k16) {
            const int kpos = k16 * 16 + tig * 4;
            uint2 aF[2][2];
            uint2 bF[4];
#pragma unroll
            for (int mf = 0; mf < 2; ++mf) {
                const int r = wm + mf * 16 + gid;
                aF[mf][0] = *(const uint2*)&Qh[r * OSTR + kpos];
                aF[mf][1] = *(const uint2*)&Qh[(r + 8) * OSTR + kpos];
            }
#pragma unroll
            for (int nf = 0; nf < 4; ++nf) {
                const int cb = wn + nf * 8 + gid;
                bF[nf] = *(const uint2*)&KVh[cb * OSTR + kpos];
            }
#pragma unroll
            for (int mf = 0; mf < 2; ++mf)
#pragma unroll
                for (int nf = 0; nf < 4; ++nf)
                    mma_f16(acc[mf][nf],
                            aF[mf][0].x, aF[mf][1].x, aF[mf][0].y, aF[mf][1].y,
                            bF[nf].x, bF[nf].y);
        }

#pragma unroll
        for (int mf = 0; mf < 2; ++mf) {
#pragma unroll
            for (int nf = 0; nf < 4; ++nf) {
                const int rl = wm + mf * 16 + gid;
                const int col = hh * 64 + wn + nf * 8 + tig * 2;
                const float z0 = zden[rl];
                const float z1 = zden[rl + 8];
                const int l_a = l0 + rl;
                const int l_b = l_a + 8;
                *(float2*)&out[((size_t)l_a * B_DIM + bb) * E_DIM + col] =
                    make_float2(acc[mf][nf][0] * z0, acc[mf][nf][1] * z0);
                *(float2*)&out[((size_t)l_b * B_DIM + bb) * E_DIM + col] =
                    make_float2(acc[mf][nf][2] * z1, acc[mf][nf][3] * z1);
            }
        }
        __syncthreads();
    }
}

// ---------------- launch ----------------
extern "C" void kernel_launch(void* const* d_in, const int* in_sizes, int n_in,
                              void* d_out, int out_size) {
    const float* q  = (const float*)d_in[0];
    const float* k  = (const float*)d_in[1];
    const float* v  = (const float*)d_in[2];
    const float* Wq = (const float*)d_in[3];
    const float* bq = (const float*)d_in[4];
    const float* Wk = (const float*)d_in[5];
    const float* bk = (const float*)d_in[6];
    const float* Wv = (const float*)d_in[7];
    const float* bv = (const float*)d_in[8];
    float* out = (float*)d_out;

    const int smem1 = 2 * SUPER * 2;                        // 98304 B
    const int smem3 = 18432 + 36864 + 512 + 512;            // 56320 B
    cudaFuncSetAttribute(gemm_qkv, cudaFuncAttributeMaxDynamicSharedMemorySize, smem1);
    cudaFuncSetAttribute(out2, cudaFuncAttributeMaxDynamicSharedMemorySize, smem3);

    preround_xw<<<dim3(4352, 3), 256>>>((const float4*)q, (const float4*)k, (const float4*)v,
                                        (const float4*)Wq, (const float4*)Wk, (const float4*)Wv);
    dim3 g1(E_DIM / 128, M_TOT / 128, 3);   // (8, 128, 3)
    gemm_qkv<<<g1, 256, smem1>>>(bq, bk, bv);
    kv2<<<dim3(NH, KCH), 256>>>();
    reduce_kv<<<dim3(NH, 9), 256>>>();
    out2<<<dim3(NH, OCH), 256, smem3>>>(out);
}